// round 1
// baseline (speedup 1.0000x reference)
#include <cuda_runtime.h>
#include <math.h>

#define DIM   768
#define HEADS 12
#define HD    64
#define B_    2
#define HH    48
#define WW    48
#define NTOK  (HH*WW)        // 2304
#define BHC   (B_*HEADS)     // 24
#define MROWS (B_*NTOK)      // 4608

// -------- scratch (device globals; no allocation allowed) --------
__device__ float g_q[BHC*NTOK*HD];   // [b,h,n,d]
__device__ float g_k[BHC*NTOK*HD];
__device__ float g_v[BHC*NTOK*HD];
__device__ float g_o[MROWS*DIM];     // [b,n, h*d]

// ====================================================================
// GEMM: C[M,N] = A[M,K] @ B[N,K]^T + bias[N]
// 128x128 tile, BK=8, 256 threads, 8x8 per thread.
// EPI==0: plain row-major write to C.
// EPI==1: scatter into g_q/g_k/g_v with [b,h,n,d] layout (QKV epilogue).
// M,N multiples of 128; K multiple of 8 (holds for all our shapes).
// ====================================================================
template<int EPI>
__global__ void __launch_bounds__(256) gemm_kernel(
    const float* __restrict__ A, const float* __restrict__ Bm,
    const float* __restrict__ bias, float* __restrict__ C,
    int M, int N, int K)
{
    __shared__ __align__(16) float As[8][128];
    __shared__ __align__(16) float Bs[8][128];

    const int tid = threadIdx.x;
    const int ty = tid >> 4, tx = tid & 15;
    const int bm = blockIdx.y * 128, bn = blockIdx.x * 128;
    const int lrow = tid >> 1;           // 0..127
    const int lcg  = (tid & 1) * 4;      // 0 or 4

    float acc[8][8] = {};

    for (int k0 = 0; k0 < K; k0 += 8) {
        float4 av = *(const float4*)&A [(size_t)(bm + lrow) * K + k0 + lcg];
        float4 bv = *(const float4*)&Bm[(size_t)(bn + lrow) * K + k0 + lcg];
        As[lcg+0][lrow] = av.x; As[lcg+1][lrow] = av.y;
        As[lcg+2][lrow] = av.z; As[lcg+3][lrow] = av.w;
        Bs[lcg+0][lrow] = bv.x; Bs[lcg+1][lrow] = bv.y;
        Bs[lcg+2][lrow] = bv.z; Bs[lcg+3][lrow] = bv.w;
        __syncthreads();

        #pragma unroll
        for (int kk = 0; kk < 8; kk++) {
            float4 a0 = *(const float4*)&As[kk][ty*8];
            float4 a1 = *(const float4*)&As[kk][ty*8+4];
            float4 b0 = *(const float4*)&Bs[kk][tx*8];
            float4 b1 = *(const float4*)&Bs[kk][tx*8+4];
            float a8[8] = {a0.x,a0.y,a0.z,a0.w,a1.x,a1.y,a1.z,a1.w};
            float b8[8] = {b0.x,b0.y,b0.z,b0.w,b1.x,b1.y,b1.z,b1.w};
            #pragma unroll
            for (int i = 0; i < 8; i++)
                #pragma unroll
                for (int j = 0; j < 8; j++)
                    acc[i][j] += a8[i] * b8[j];
        }
        __syncthreads();
    }

    if (EPI == 0) {
        #pragma unroll
        for (int i = 0; i < 8; i++) {
            int m = bm + ty*8 + i;
            #pragma unroll
            for (int j = 0; j < 8; j++) {
                int c = bn + tx*8 + j;
                C[(size_t)m * N + c] = acc[i][j] + bias[c];
            }
        }
    } else {
        #pragma unroll
        for (int i = 0; i < 8; i++) {
            int m = bm + ty*8 + i;
            int b = m / NTOK;
            int pos = m - b * NTOK;
            #pragma unroll
            for (int j = 0; j < 8; j++) {
                int c = bn + tx*8 + j;
                float val = acc[i][j] + bias[c];
                int which = c / DIM;
                int rem = c - which * DIM;
                int h = rem >> 6;       // /64
                int d = rem & 63;
                float* dst = (which == 0) ? g_q : (which == 1) ? g_k : g_v;
                dst[((size_t)(b*HEADS + h) * NTOK + pos) * HD + d] = val;
            }
        }
    }
}

// ====================================================================
// RoPE (in place on g_q, g_k). One thread per (arr, bh, n, d<32) pair.
// angle[n, j] for j in [0,32): axis = j/16, p = j%16;
// coord = 2*((idx+0.5)/48) - 1 ; angle = 2*pi*coord / 100^(p/16)
// angles duplicated to [0,64): cos/sin same for d and d+32.
// q'[d]    = q[d]*cos    - q[d+32]*sin
// q'[d+32] = q[d+32]*cos + q[d]*sin
// ====================================================================
#define ROPE_PAIRS (BHC * NTOK * 32)

__global__ void __launch_bounds__(256) rope_kernel()
{
    int idx = blockIdx.x * 256 + threadIdx.x;
    if (idx >= 2 * ROPE_PAIRS) return;
    int a = idx / ROPE_PAIRS;
    int r = idx - a * ROPE_PAIRS;
    int bh = r / (NTOK * 32);
    int r2 = r - bh * (NTOK * 32);
    int n = r2 >> 5;
    int d = r2 & 31;

    int axis = d >> 4;
    int p    = d & 15;
    int y = n / WW, x = n - y * WW;
    float idxf  = axis == 0 ? (float)y : (float)x;
    float coord = 2.0f * ((idxf + 0.5f) / 48.0f) - 1.0f;
    // period = 100^(p/16)  ->  exp2f(p * log2(100)/16)
    float period = exp2f((float)p * (6.643856189774725f / 16.0f));
    float ang = 6.283185307179586f * coord / period;
    float sn, cs;
    sincosf(ang, &sn, &cs);

    float* arr = (a == 0) ? g_q : g_k;
    size_t base = ((size_t)bh * NTOK + n) * HD;
    float v0 = arr[base + d];
    float v1 = arr[base + d + 32];
    arr[base + d]      = v0 * cs - v1 * sn;
    arr[base + d + 32] = v1 * cs + v0 * sn;
}

// ====================================================================
// Flash-style fp32 attention.
// Grid: (NTOK/64, BHC). Block: 256 threads (16x16).
// CTA: 64 query rows, streams keys in tiles of 32, online softmax.
// Thread owns: S tile 4 rows x 2 cols; O tile 4 rows x 4 cols.
// ====================================================================
__global__ void __launch_bounds__(256) attn_kernel()
{
    __shared__ __align__(16) float Qs[64][65];
    __shared__ __align__(16) float Ks[32][65];
    __shared__ __align__(16) float Vs[32][65];
    __shared__ float Ps[64][33];

    const int tid = threadIdx.x;
    const int ty = tid >> 4, tx = tid & 15;
    const int bh = blockIdx.y;
    const int q0 = blockIdx.x * 64;

    const float* Qg = g_q + ((size_t)bh * NTOK + q0) * HD;
    const float* Kg = g_k + (size_t)bh * NTOK * HD;
    const float* Vg = g_v + (size_t)bh * NTOK * HD;

    // load Q tile (64x64)
    #pragma unroll
    for (int t = 0; t < 4; t++) {
        int lin = t * 256 + tid;
        int row = lin >> 4, g = (lin & 15) * 4;
        float4 v = *(const float4*)&Qg[row * HD + g];
        Qs[row][g] = v.x; Qs[row][g+1] = v.y; Qs[row][g+2] = v.z; Qs[row][g+3] = v.w;
    }

    float o[4][4] = {};
    float mi[4], li[4];
    #pragma unroll
    for (int i = 0; i < 4; i++) { mi[i] = -1e30f; li[i] = 0.0f; }
    const float scale = 0.125f;   // 1/sqrt(64)

    for (int k0 = 0; k0 < NTOK; k0 += 32) {
        __syncthreads();   // Q ready (iter0) / prev P@V reads done
        // load K,V tiles (32x64 each)
        #pragma unroll
        for (int t = 0; t < 2; t++) {
            int lin = t * 256 + tid;
            int row = lin >> 4, g = (lin & 15) * 4;
            float4 kv = *(const float4*)&Kg[(size_t)(k0 + row) * HD + g];
            Ks[row][g] = kv.x; Ks[row][g+1] = kv.y; Ks[row][g+2] = kv.z; Ks[row][g+3] = kv.w;
            float4 vv = *(const float4*)&Vg[(size_t)(k0 + row) * HD + g];
            Vs[row][g] = vv.x; Vs[row][g+1] = vv.y; Vs[row][g+2] = vv.z; Vs[row][g+3] = vv.w;
        }
        __syncthreads();

        // S = Q @ K^T  (64x32), thread: 4 rows x 2 cols
        float s[4][2] = {};
        #pragma unroll 8
        for (int d = 0; d < 64; d++) {
            float qv[4], kv2[2];
            #pragma unroll
            for (int i = 0; i < 4; i++) qv[i] = Qs[ty*4+i][d];
            #pragma unroll
            for (int j = 0; j < 2; j++) kv2[j] = Ks[tx*2+j][d];
            #pragma unroll
            for (int i = 0; i < 4; i++)
                #pragma unroll
                for (int j = 0; j < 2; j++)
                    s[i][j] += qv[i] * kv2[j];
        }

        // online softmax update
        #pragma unroll
        for (int i = 0; i < 4; i++) {
            s[i][0] *= scale; s[i][1] *= scale;
            float rm = fmaxf(s[i][0], s[i][1]);
            #pragma unroll
            for (int off = 1; off < 16; off <<= 1)
                rm = fmaxf(rm, __shfl_xor_sync(0xffffffffu, rm, off));
            float nm = fmaxf(mi[i], rm);
            float p0 = __expf(s[i][0] - nm);
            float p1 = __expf(s[i][1] - nm);
            float rs = p0 + p1;
            #pragma unroll
            for (int off = 1; off < 16; off <<= 1)
                rs += __shfl_xor_sync(0xffffffffu, rs, off);
            float f = __expf(mi[i] - nm);
            li[i] = li[i] * f + rs;
            mi[i] = nm;
            #pragma unroll
            for (int j = 0; j < 4; j++) o[i][j] *= f;
            Ps[ty*4+i][tx*2+0] = p0;
            Ps[ty*4+i][tx*2+1] = p1;
        }
        __syncthreads();

        // O += P @ V  (64x64), thread: 4 rows x 4 cols
        #pragma unroll 4
        for (int k = 0; k < 32; k++) {
            float pv[4], vv2[4];
            #pragma unroll
            for (int i = 0; i < 4; i++) pv[i] = Ps[ty*4+i][k];
            #pragma unroll
            for (int j = 0; j < 4; j++) vv2[j] = Vs[k][tx*4+j];
            #pragma unroll
            for (int i = 0; i < 4; i++)
                #pragma unroll
                for (int j = 0; j < 4; j++)
                    o[i][j] += pv[i] * vv2[j];
        }
    }

    // write O (normalized) to g_o in [b, n, h*d] layout
    int b = bh / HEADS, h = bh - b * HEADS;
    #pragma unroll
    for (int i = 0; i < 4; i++) {
        int pos = q0 + ty*4 + i;
        float inv = 1.0f / li[i];
        #pragma unroll
        for (int j = 0; j < 4; j++) {
            g_o[((size_t)(b*NTOK + pos)) * DIM + h*HD + tx*4 + j] = o[i][j] * inv;
        }
    }
}

// ====================================================================
// launcher
// ====================================================================
extern "C" void kernel_launch(void* const* d_in, const int* in_sizes, int n_in,
                              void* d_out, int out_size)
{
    const float* x      = (const float*)d_in[0];
    const float* w_qkv  = (const float*)d_in[1];
    const float* b_qkv  = (const float*)d_in[2];
    const float* w_proj = (const float*)d_in[3];
    const float* b_proj = (const float*)d_in[4];
    float* out = (float*)d_out;

    void* p_go = nullptr;
    cudaGetSymbolAddress(&p_go, g_o);

    // 1) QKV GEMM + bias, scatter to [b,h,n,d] Q/K/V
    gemm_kernel<1><<<dim3(3*DIM/128, MROWS/128), 256>>>(
        x, w_qkv, b_qkv, nullptr, MROWS, 3*DIM, DIM);

    // 2) RoPE on Q and K
    int rope_threads = 2 * ROPE_PAIRS;
    rope_kernel<<<(rope_threads + 255) / 256, 256>>>();

    // 3) attention
    attn_kernel<<<dim3(NTOK/64, BHC), 256>>>();

    // 4) output projection -> d_out
    gemm_kernel<0><<<dim3(DIM/128, MROWS/128), 256>>>(
        (const float*)p_go, w_proj, b_proj, out, MROWS, DIM, DIM);
}

// round 2
// speedup vs baseline: 1.0463x; 1.0463x over previous
#include <cuda_runtime.h>
#include <math.h>

#define DIM   768
#define HEADS 12
#define HD    64
#define B_    2
#define HH    48
#define WW    48
#define NTOK  (HH*WW)        // 2304
#define BHC   (B_*HEADS)     // 24
#define MROWS (B_*NTOK)      // 4608

// -------- scratch (device globals; no allocation allowed) --------
__device__ float g_q[BHC*NTOK*HD];   // [b,h,n,d]
__device__ float g_k[BHC*NTOK*HD];
__device__ float g_v[BHC*NTOK*HD];
__device__ float g_o[MROWS*DIM];     // [b,n, h*d]

// ====================================================================
// GEMM: C[M,N] = A[M,K] @ B[N,K]^T + bias[N]
// 128x128 tile, BK=8 double-buffered, 256 threads, 8x8 per thread.
// EPI==0: plain row-major write.
// EPI==1: QKV epilogue -> fused RoPE (on q,k) + scatter to [b,h,n,d].
// ====================================================================
template<int EPI>
__global__ void __launch_bounds__(256) gemm_kernel(
    const float* __restrict__ A, const float* __restrict__ Bm,
    const float* __restrict__ bias, float* __restrict__ C,
    int M, int N, int K)
{
    __shared__ __align__(16) float As[2][8][128];
    __shared__ __align__(16) float Bs[2][8][128];

    const int tid = threadIdx.x;
    const int ty = tid >> 4, tx = tid & 15;
    const int bm = blockIdx.y * 128, bn = blockIdx.x * 128;
    const int lrow = tid >> 1;           // 0..127
    const int lcg  = (tid & 1) * 4;      // 0 or 4

    float acc[8][8] = {};

    // prologue: load tile 0 into buffer 0
    {
        float4 av = *(const float4*)&A [(size_t)(bm + lrow) * K + lcg];
        float4 bv = *(const float4*)&Bm[(size_t)(bn + lrow) * K + lcg];
        As[0][lcg+0][lrow] = av.x; As[0][lcg+1][lrow] = av.y;
        As[0][lcg+2][lrow] = av.z; As[0][lcg+3][lrow] = av.w;
        Bs[0][lcg+0][lrow] = bv.x; Bs[0][lcg+1][lrow] = bv.y;
        Bs[0][lcg+2][lrow] = bv.z; Bs[0][lcg+3][lrow] = bv.w;
    }
    __syncthreads();

    int buf = 0;
    for (int k0 = 0; k0 < K; k0 += 8) {
        const bool more = (k0 + 8) < K;
        float4 av, bv;
        if (more) {
            av = *(const float4*)&A [(size_t)(bm + lrow) * K + k0 + 8 + lcg];
            bv = *(const float4*)&Bm[(size_t)(bn + lrow) * K + k0 + 8 + lcg];
        }

        #pragma unroll
        for (int kk = 0; kk < 8; kk++) {
            float4 a0 = *(const float4*)&As[buf][kk][ty*8];
            float4 a1 = *(const float4*)&As[buf][kk][ty*8+4];
            float4 b0 = *(const float4*)&Bs[buf][kk][tx*8];
            float4 b1 = *(const float4*)&Bs[buf][kk][tx*8+4];
            float a8[8] = {a0.x,a0.y,a0.z,a0.w,a1.x,a1.y,a1.z,a1.w};
            float b8[8] = {b0.x,b0.y,b0.z,b0.w,b1.x,b1.y,b1.z,b1.w};
            #pragma unroll
            for (int i = 0; i < 8; i++)
                #pragma unroll
                for (int j = 0; j < 8; j++)
                    acc[i][j] += a8[i] * b8[j];
        }

        if (more) {
            int nb = buf ^ 1;
            As[nb][lcg+0][lrow] = av.x; As[nb][lcg+1][lrow] = av.y;
            As[nb][lcg+2][lrow] = av.z; As[nb][lcg+3][lrow] = av.w;
            Bs[nb][lcg+0][lrow] = bv.x; Bs[nb][lcg+1][lrow] = bv.y;
            Bs[nb][lcg+2][lrow] = bv.z; Bs[nb][lcg+3][lrow] = bv.w;
        }
        __syncthreads();
        buf ^= 1;
    }

    if (EPI == 0) {
        #pragma unroll
        for (int i = 0; i < 8; i++) {
            int m = bm + ty*8 + i;
            #pragma unroll
            for (int j = 0; j < 8; j++) {
                int c = bn + tx*8 + j;
                C[(size_t)m * N + c] = acc[i][j] + bias[c];
            }
        }
    } else {
        // QKV epilogue with fused RoPE.
        // Pair column for RoPE is c ^ 32 -> owned by lane (tx^4) in same warp.
        #pragma unroll
        for (int i = 0; i < 8; i++) {
            int m = bm + ty*8 + i;
            int b = m / NTOK;
            int pos = m - b * NTOK;
            int ypix = pos / WW, xpix = pos - ypix * WW;

            float val[8];
            #pragma unroll
            for (int j = 0; j < 8; j++)
                val[j] = acc[i][j] + bias[bn + tx*8 + j];
            float pairv[8];
            #pragma unroll
            for (int j = 0; j < 8; j++)
                pairv[j] = __shfl_xor_sync(0xffffffffu, val[j], 4);

            #pragma unroll
            for (int j = 0; j < 8; j++) {
                int c = bn + tx*8 + j;
                int which = c / DIM;
                int rem = c - which * DIM;
                int h = rem >> 6;
                int d = rem & 63;
                float outv = val[j];
                if (which < 2) {
                    int p    = d & 15;
                    int axis = (d >> 4) & 1;
                    float idxf  = axis ? (float)xpix : (float)ypix;
                    float coord = 2.0f * ((idxf + 0.5f) / 48.0f) - 1.0f;
                    // invperiod = 100^(-p/16) = exp2(-p * log2(100)/16)
                    float invp = exp2f(-(float)p * 0.41524101186092607f);
                    float ang = 6.283185307179586f * coord * invp;
                    float sn, cs;
                    sincosf(ang, &sn, &cs);
                    outv = (d & 32) ? (val[j]*cs + pairv[j]*sn)
                                    : (val[j]*cs - pairv[j]*sn);
                }
                float* dst = (which == 0) ? g_q : (which == 1) ? g_k : g_v;
                dst[((size_t)(b*HEADS + h) * NTOK + pos) * HD + d] = outv;
            }
        }
    }
}

// ====================================================================
// Flash-style fp32 attention, v2.
// Grid: (NTOK/128, BHC). Block: 256 threads.
// CTA: 128 query rows, key tiles of 64, online softmax.
// Thread (ty=tid/8 in 0..31, tx=tid%8): 4 rows x 8 cols for S and O.
// Smem (dynamic, 100KB): transposed layouts for broadcast-friendly float4.
//   Qs_t[64][132]  (d-major, 128 rows)
//   Ks_t[64][68]   (d-major, 64 keys)
//   Vs  [64][68]   (natural)
//   Ps_t[64][132]  (k-major, 128 rows)
// ====================================================================
#define QS_OFF 0
#define KS_OFF (64*132)
#define VS_OFF (KS_OFF + 64*68)
#define PS_OFF (VS_OFF + 64*68)
#define ATTN_SMEM_FLOATS (PS_OFF + 64*132)
#define ATTN_SMEM_BYTES  (ATTN_SMEM_FLOATS * 4)

__global__ void __launch_bounds__(256, 2) attn_kernel()
{
    extern __shared__ __align__(16) float sm[];
    float* Qs = sm + QS_OFF;   // [d][row], stride 132
    float* Ks = sm + KS_OFF;   // [d][key], stride 68
    float* Vs = sm + VS_OFF;   // [key][d], stride 68
    float* Ps = sm + PS_OFF;   // [key][row], stride 132

    const int tid = threadIdx.x;
    const int ty = tid >> 3;      // 0..31
    const int tx = tid & 7;       // 0..7
    const int ty4 = ty * 4;
    const int tx8 = tx * 8;
    const int bh = blockIdx.y;
    const int q0 = blockIdx.x * 128;

    const float* Qg = g_q + ((size_t)bh * NTOK + q0) * HD;
    const float* Kg = g_k + (size_t)bh * NTOK * HD;
    const float* Vg = g_v + (size_t)bh * NTOK * HD;

    // load Q tile (128 x 64), transposed into Qs[d][row]
    #pragma unroll
    for (int t = 0; t < 8; t++) {
        int lin = t * 256 + tid;
        int row = lin >> 4, g = (lin & 15) * 4;
        float4 v = *(const float4*)&Qg[(size_t)row * HD + g];
        Qs[(g+0)*132 + row] = v.x; Qs[(g+1)*132 + row] = v.y;
        Qs[(g+2)*132 + row] = v.z; Qs[(g+3)*132 + row] = v.w;
    }

    float o[4][8] = {};
    float mi[4], li[4];
    #pragma unroll
    for (int i = 0; i < 4; i++) { mi[i] = -1e30f; li[i] = 0.0f; }
    const float scale = 0.125f;   // 1/sqrt(64)

    for (int k0 = 0; k0 < NTOK; k0 += 64) {
        // global loads for this tile (4 float4 each of K and V per thread)
        float4 kr[4], vr[4];
        #pragma unroll
        for (int t = 0; t < 4; t++) {
            int lin = t * 256 + tid;
            int row = lin >> 4, g = (lin & 15) * 4;
            kr[t] = *(const float4*)&Kg[(size_t)(k0 + row) * HD + g];
            vr[t] = *(const float4*)&Vg[(size_t)(k0 + row) * HD + g];
        }
        __syncthreads();   // prev-iter readers of Ks/Vs/Ps done (also covers Q on iter 0)
        #pragma unroll
        for (int t = 0; t < 4; t++) {
            int lin = t * 256 + tid;
            int row = lin >> 4, g = (lin & 15) * 4;
            Ks[(g+0)*68 + row] = kr[t].x; Ks[(g+1)*68 + row] = kr[t].y;
            Ks[(g+2)*68 + row] = kr[t].z; Ks[(g+3)*68 + row] = kr[t].w;
            *(float4*)&Vs[row*68 + g] = vr[t];
        }
        __syncthreads();

        // S = Q @ K^T  (128 x 64); thread: 4 rows x 8 cols
        float s[4][8] = {};
        #pragma unroll 8
        for (int d = 0; d < 64; d++) {
            float4 q4 = *(const float4*)&Qs[d*132 + ty4];
            float4 k0v = *(const float4*)&Ks[d*68 + tx8];
            float4 k1v = *(const float4*)&Ks[d*68 + tx8 + 4];
            float qv[4] = {q4.x, q4.y, q4.z, q4.w};
            float kv[8] = {k0v.x,k0v.y,k0v.z,k0v.w,k1v.x,k1v.y,k1v.z,k1v.w};
            #pragma unroll
            for (int i = 0; i < 4; i++)
                #pragma unroll
                for (int j = 0; j < 8; j++)
                    s[i][j] += qv[i] * kv[j];
        }

        // online softmax (reduce over tx group of 8 lanes)
        #pragma unroll
        for (int i = 0; i < 4; i++) {
            float rm = -1e30f;
            #pragma unroll
            for (int j = 0; j < 8; j++) { s[i][j] *= scale; rm = fmaxf(rm, s[i][j]); }
            #pragma unroll
            for (int off = 1; off < 8; off <<= 1)
                rm = fmaxf(rm, __shfl_xor_sync(0xffffffffu, rm, off));
            float nm = fmaxf(mi[i], rm);
            float rs = 0.0f;
            #pragma unroll
            for (int j = 0; j < 8; j++) { s[i][j] = __expf(s[i][j] - nm); rs += s[i][j]; }
            #pragma unroll
            for (int off = 1; off < 8; off <<= 1)
                rs += __shfl_xor_sync(0xffffffffu, rs, off);
            float f = __expf(mi[i] - nm);
            li[i] = li[i] * f + rs;
            mi[i] = nm;
            #pragma unroll
            for (int j = 0; j < 8; j++) o[i][j] *= f;
        }
        // write P transposed: Ps[key][row], one float4 (4 rows) per col
        #pragma unroll
        for (int c = 0; c < 8; c++) {
            float4 pv = make_float4(s[0][c], s[1][c], s[2][c], s[3][c]);
            *(float4*)&Ps[(tx8 + c)*132 + ty4] = pv;
        }
        __syncthreads();

        // O += P @ V  (128 x 64); thread: 4 rows x 8 cols
        #pragma unroll 8
        for (int k = 0; k < 64; k++) {
            float4 p4 = *(const float4*)&Ps[k*132 + ty4];
            float4 v0 = *(const float4*)&Vs[k*68 + tx8];
            float4 v1 = *(const float4*)&Vs[k*68 + tx8 + 4];
            float pv[4] = {p4.x, p4.y, p4.z, p4.w};
            float vv[8] = {v0.x,v0.y,v0.z,v0.w,v1.x,v1.y,v1.z,v1.w};
            #pragma unroll
            for (int i = 0; i < 4; i++)
                #pragma unroll
                for (int j = 0; j < 8; j++)
                    o[i][j] += pv[i] * vv[j];
        }
    }

    // write O (normalized) to g_o in [b, n, h*d] layout
    int b = bh / HEADS, h = bh - b * HEADS;
    #pragma unroll
    for (int i = 0; i < 4; i++) {
        int pos = q0 + ty4 + i;
        float inv = 1.0f / li[i];
        float* dst = &g_o[((size_t)(b*NTOK + pos)) * DIM + h*HD + tx8];
        float4 o0 = make_float4(o[i][0]*inv, o[i][1]*inv, o[i][2]*inv, o[i][3]*inv);
        float4 o1 = make_float4(o[i][4]*inv, o[i][5]*inv, o[i][6]*inv, o[i][7]*inv);
        *(float4*)&dst[0] = o0;
        *(float4*)&dst[4] = o1;
    }
}

// ====================================================================
// launcher
// ====================================================================
extern "C" void kernel_launch(void* const* d_in, const int* in_sizes, int n_in,
                              void* d_out, int out_size)
{
    const float* x      = (const float*)d_in[0];
    const float* w_qkv  = (const float*)d_in[1];
    const float* b_qkv  = (const float*)d_in[2];
    const float* w_proj = (const float*)d_in[3];
    const float* b_proj = (const float*)d_in[4];
    float* out = (float*)d_out;

    void* p_go = nullptr;
    cudaGetSymbolAddress(&p_go, g_o);

    static bool attr_set = false;
    if (!attr_set) {
        cudaFuncSetAttribute(attn_kernel,
                             cudaFuncAttributeMaxDynamicSharedMemorySize,
                             ATTN_SMEM_BYTES);
        attr_set = true;
    }

    // 1) QKV GEMM + bias + fused RoPE, scatter to [b,h,n,d] Q/K/V
    gemm_kernel<1><<<dim3(3*DIM/128, MROWS/128), 256>>>(
        x, w_qkv, b_qkv, nullptr, MROWS, 3*DIM, DIM);

    // 2) attention
    attn_kernel<<<dim3(NTOK/128, BHC), 256, ATTN_SMEM_BYTES>>>();

    // 3) output projection -> d_out
    gemm_kernel<0><<<dim3(DIM/128, MROWS/128), 256>>>(
        (const float*)p_go, w_proj, b_proj, out, MROWS, DIM, DIM);
}